// round 15
// baseline (speedup 1.0000x reference)
#include <cuda_runtime.h>
#include <cuda_bf16.h>
#include <math.h>
#include <stdint.h>

// Problem constants
#define BATCH 256
#define TLEN  512
#define DIM   1024
#define VOCAB 32000

// Persistent tiling: 128 CTAs (1/SM);
//   bid -> mb = bid&3 (64-row block), nc = (bid>>2)&7 (128-col tile), kc = bid>>5 (K=256 slab)
#define NK 4
#define KT 256
#define NT 128
#define NCTA 128

// SMEM layout (scan):
#define SM_W    0
#define W_SPL   69632u
#define WSTRIDE 272u
#define SM_A    139264
#define ASPL    33792u
#define ASTRIDE 528u
#define SMEM_BYTES (139264 + 67584)   // 206848

// SMEM layout (logits): B chunk [2 spl][128 k][136] stride 272; A chunk [2 spl][64 m][136]
#define LG_B     0
#define LG_BSPL  34816u
#define LG_A     69632
#define LG_ASPL  17408u
#define LG_STR   272u
#define LG_SMEM  (69632 + 34816)      // 104448

// ---------------------------------------------------------------------------
// Device scratch (static — no cudaMalloc allowed)
// ---------------------------------------------------------------------------
__device__ float         g_P[NK][BATCH][DIM];     // partial sums
__device__ __nv_bfloat16 g_Uhi[BATCH][DIM], g_Ulo[BATCH][DIM];  // u splits; z splits after scan
__device__ __nv_bfloat16 g_Hhi[BATCH][DIM], g_Hlo[BATCH][DIM];
__device__ unsigned g_bar_arrive = 0;
__device__ unsigned g_bar_gen    = 0;

// ---------------------------------------------------------------------------
// PTX helpers
// ---------------------------------------------------------------------------
__device__ __forceinline__ uint32_t smem_u32(const void* p) {
    uint32_t a;
    asm("{ .reg .u64 t; cvta.to.shared.u64 t, %1; cvt.u32.u64 %0, t; }" : "=r"(a) : "l"(p));
    return a;
}
__device__ __forceinline__ void cp_async16(uint32_t dst, const void* src) {
    asm volatile("cp.async.cg.shared.global [%0], [%1], 16;" :: "r"(dst), "l"(src) : "memory");
}
#define CP_COMMIT() asm volatile("cp.async.commit_group;" ::: "memory")
#define CP_WAIT(n)  asm volatile("cp.async.wait_group %0;" :: "n"(n) : "memory")

__device__ __forceinline__ void ldm_x4(uint32_t* r, uint32_t addr) {
    asm volatile("ldmatrix.sync.aligned.m8n8.x4.shared.b16 {%0,%1,%2,%3}, [%4];"
                 : "=r"(r[0]), "=r"(r[1]), "=r"(r[2]), "=r"(r[3]) : "r"(addr));
}
__device__ __forceinline__ void ldm_x2_t(uint32_t* r, uint32_t addr) {
    asm volatile("ldmatrix.sync.aligned.m8n8.x2.trans.shared.b16 {%0,%1}, [%2];"
                 : "=r"(r[0]), "=r"(r[1]) : "r"(addr));
}
__device__ __forceinline__ void mma_bf16(float* c, const uint32_t* a, const uint32_t* b) {
    asm volatile(
        "mma.sync.aligned.m16n8k16.row.col.f32.bf16.bf16.f32 "
        "{%0,%1,%2,%3}, {%4,%5,%6,%7}, {%8,%9}, {%0,%1,%2,%3};"
        : "+f"(c[0]), "+f"(c[1]), "+f"(c[2]), "+f"(c[3])
        : "r"(a[0]), "r"(a[1]), "r"(a[2]), "r"(a[3]), "r"(b[0]), "r"(b[1]));
}
__device__ __forceinline__ uint32_t pack_bf16x2(float a, float b) {
    const __nv_bfloat16 ba = __float2bfloat16(a);
    const __nv_bfloat16 bb = __float2bfloat16(b);
    return (uint32_t)__bfloat16_as_ushort(ba) | ((uint32_t)__bfloat16_as_ushort(bb) << 16);
}
__device__ __forceinline__ void split_store8(__nv_bfloat16* hp, __nv_bfloat16* lp,
                                             const float* v)
{
    uint32_t h[4], l[4];
    #pragma unroll
    for (int q = 0; q < 4; ++q) {
        const float a = v[2*q], b = v[2*q+1];
        h[q] = pack_bf16x2(a, b);
        const float la = a - __bfloat162float(__float2bfloat16(a));
        const float lb = b - __bfloat162float(__float2bfloat16(b));
        l[q] = pack_bf16x2(la, lb);
    }
    __stcg((uint4*)hp, make_uint4(h[0], h[1], h[2], h[3]));
    __stcg((uint4*)lp, make_uint4(l[0], l[1], l[2], l[3]));
}

// ---------------------------------------------------------------------------
// Grid-wide barrier (R11/R14-proven)
// ---------------------------------------------------------------------------
__device__ __forceinline__ void grid_barrier()
{
    __threadfence();
    __syncthreads();
    if (threadIdx.x == 0) {
        unsigned gen = *(volatile unsigned*)&g_bar_gen;
        if (atomicAdd(&g_bar_arrive, 1u) == NCTA - 1u) {
            atomicExch(&g_bar_arrive, 0u);
            __threadfence();
            atomicAdd(&g_bar_gen, 1u);
        } else {
            while (*(volatile unsigned*)&g_bar_gen == gen) { }
        }
        __threadfence();
    }
    __syncthreads();
}

// ---------------------------------------------------------------------------
// W tile load: fp32 Wdt -> smem bf16 hi/lo, [256 k][128 n] stride 272B
// ---------------------------------------------------------------------------
__device__ __forceinline__ void load_w(char* smp, const float* __restrict__ Wdt,
                                       int half, int k0, int n0, int tid)
{
    for (int i = tid; i < KT * NT; i += 256) {
        const int k = i >> 7;
        const int n = i & 127;
        const float v = Wdt[(size_t)(half * DIM + k0 + k) * DIM + n0 + n];
        const __nv_bfloat16 hi = __float2bfloat16(v);
        const __nv_bfloat16 lo = __float2bfloat16(v - __bfloat162float(hi));
        *(__nv_bfloat16*)(smp + SM_W + (uint32_t)k * WSTRIDE + (uint32_t)n * 2u) = hi;
        *(__nv_bfloat16*)(smp + SM_W + W_SPL + (uint32_t)k * WSTRIDE + (uint32_t)n * 2u) = lo;
    }
}

// cp.async one K=128 half of A (hi+lo): 64 rows x 256B x 2 splits = 2048 x 16B
__device__ __forceinline__ void issue_half(uint32_t sa_base,
    const __nv_bfloat16* __restrict__ srchi, const __nv_bfloat16* __restrict__ srclo,
    int m0, int kglob, uint32_t dcol, int tid)
{
    #pragma unroll
    for (int t = 0; t < 8; ++t) {
        const int i  = tid + t * 256;
        const int sp = i >> 10;
        const int r  = (i >> 4) & 63;
        const int c  = i & 15;
        const __nv_bfloat16* src =
            (sp ? srclo : srchi) + (size_t)(m0 + r) * DIM + kglob + c * 8;
        const uint32_t dst = sa_base + (uint32_t)sp * ASPL
                           + (uint32_t)r * ASTRIDE + dcol + (uint32_t)c * 16u;
        cp_async16(dst, src);
    }
    CP_COMMIT();
}

// ---------------------------------------------------------------------------
// Compute 8 ksteps (one K=128 half): warp (mw = wid&3, nw = wid>>2)
// ---------------------------------------------------------------------------
__device__ __forceinline__ void compute_half(uint32_t abase, uint32_t wbase, int ks0,
                                             float acc[8][4], int lane, int mw, int nw)
{
    #pragma unroll
    for (int ks = ks0; ks < ks0 + 8; ++ks) {
        const uint32_t arow = (uint32_t)(mw * 16 + (lane & 15));
        const uint32_t acol = (uint32_t)(ks * 32 + (lane >> 4) * 16);
        uint32_t ah[4], al[4];
        {
            const uint32_t off = arow * ASTRIDE + acol;
            ldm_x4(ah, abase + off);
            ldm_x4(al, abase + ASPL + off);
        }
        const uint32_t krow_b = (uint32_t)(ks * 16 + (lane & 15));
        #pragma unroll
        for (int g = 0; g < 2; ++g) {
            uint32_t bh[4][2], bl[4][2];
            #pragma unroll
            for (int j = 0; j < 4; ++j) {
                const uint32_t nb = (uint32_t)(nw * 128 + (g * 4 + j) * 16);
                ldm_x2_t(bh[j], wbase + 0u    + krow_b * WSTRIDE + nb);
                ldm_x2_t(bl[j], wbase + W_SPL + krow_b * WSTRIDE + nb);
            }
            #pragma unroll
            for (int j = 0; j < 4; ++j) {
                float* a = acc[g * 4 + j];
                mma_bf16(a, ah, bh[j]);
                mma_bf16(a, ah, bl[j]);
                mma_bf16(a, al, bh[j]);
            }
        }
    }
}

// ---------------------------------------------------------------------------
// One full step GEMM: P[kc][m0..m0+63][n0..n0+127] over K [k0, k0+256)
// ---------------------------------------------------------------------------
__device__ __forceinline__ void gemm_step_mma(char* smp, uint32_t base,
    const __nv_bfloat16* __restrict__ srchi, const __nv_bfloat16* __restrict__ srclo,
    int m0, int k0, int n0, int kc, int tid)
{
    const int lane = tid & 31, wid = tid >> 5;
    const int mw = wid & 3, nw = wid >> 2;
    float acc[8][4];
    #pragma unroll
    for (int nt = 0; nt < 8; ++nt)
        #pragma unroll
        for (int q = 0; q < 4; ++q) acc[nt][q] = 0.f;

    const uint32_t ab = base + SM_A;
    const uint32_t wb = base + SM_W;

    issue_half(ab, srchi, srclo, m0, k0 + 0,   0u,   tid);
    issue_half(ab, srchi, srclo, m0, k0 + 128, 256u, tid);

    CP_WAIT(1); __syncthreads();
    compute_half(ab, wb, 0, acc, lane, mw, nw);
    CP_WAIT(0); __syncthreads();
    compute_half(ab, wb, 8, acc, lane, mw, nw);

    const int r4 = lane >> 2, c2 = (lane & 3) * 2;
    #pragma unroll
    for (int nt = 0; nt < 8; ++nt) {
        const int r0 = m0 + mw * 16 + r4;
        const int cc = n0 + nw * 64 + nt * 8 + c2;
        __stcg((float2*)&g_P[kc][r0][cc],     make_float2(acc[nt][0], acc[nt][1]));
        __stcg((float2*)&g_P[kc][r0 + 8][cc], make_float2(acc[nt][2], acc[nt][3]));
    }
}

// ---------------------------------------------------------------------------
// Persistent scan kernel (R14, unchanged except z-split store at last step)
// ---------------------------------------------------------------------------
__global__ __launch_bounds__(256) void rnn_persistent(
    const float* __restrict__ hidden, const int* __restrict__ tok,
    const float* __restrict__ emb,    const float* __restrict__ Wdt,
    const float* __restrict__ bdt,    const float* __restrict__ gamma,
    const float* __restrict__ beta,   float* __restrict__ zout)
{
    extern __shared__ char smp[];
    const uint32_t base = smem_u32(smp);
    __shared__ float red[2][2][4];

    const int tid = threadIdx.x;
    const int bid = blockIdx.x;
    const int mb = bid & 3, nc = (bid >> 2) & 7, kc = bid >> 5;
    const int m0 = mb * 64, n0 = nc * NT, k0 = kc * KT;

    const int row_sel = tid >> 7;
    const int b  = bid * 2 + row_sel;
    const int lt = tid & 127;
    const int d0 = lt * 8;
    const int wr = (tid >> 5) & 3;

    float ur[8], gm[8], bt[8];
    {
        const int tk0 = tok[(size_t)b * TLEN];
        float hv[8];
        const float4 h0 = *(const float4*)&hidden[(size_t)b * DIM + d0];
        const float4 h1 = *(const float4*)&hidden[(size_t)b * DIM + d0 + 4];
        hv[0]=h0.x; hv[1]=h0.y; hv[2]=h0.z; hv[3]=h0.w;
        hv[4]=h1.x; hv[5]=h1.y; hv[6]=h1.z; hv[7]=h1.w;
        const float4 u0 = *(const float4*)&emb[(size_t)tk0 * DIM + d0];
        const float4 u1 = *(const float4*)&emb[(size_t)tk0 * DIM + d0 + 4];
        ur[0]=u0.x; ur[1]=u0.y; ur[2]=u0.z; ur[3]=u0.w;
        ur[4]=u1.x; ur[5]=u1.y; ur[6]=u1.z; ur[7]=u1.w;
        split_store8(&g_Hhi[b][d0], &g_Hlo[b][d0], hv);
        split_store8(&g_Uhi[b][d0], &g_Ulo[b][d0], ur);
        const float4 g0 = *(const float4*)&gamma[d0];
        const float4 g1 = *(const float4*)&gamma[d0 + 4];
        gm[0]=g0.x; gm[1]=g0.y; gm[2]=g0.z; gm[3]=g0.w;
        gm[4]=g1.x; gm[5]=g1.y; gm[6]=g1.z; gm[7]=g1.w;
        const float4 b0 = *(const float4*)&beta[d0];
        const float4 b1 = *(const float4*)&beta[d0 + 4];
        bt[0]=b0.x; bt[1]=b0.y; bt[2]=b0.z; bt[3]=b0.w;
        bt[4]=b1.x; bt[5]=b1.y; bt[6]=b1.z; bt[7]=b1.w;
    }

    load_w(smp, Wdt, 1, k0, n0, tid);
    grid_barrier();
    gemm_step_mma(smp, base, &g_Hhi[0][0], &g_Hlo[0][0], m0, k0, n0, kc, tid);
    grid_barrier();

    float cre[8];
    {
        #pragma unroll
        for (int j = 0; j < 8; ++j) cre[j] = 0.f;
        #pragma unroll
        for (int j = 0; j < NK; ++j) {
            const float4 p0 = __ldcg((const float4*)&g_P[j][b][d0]);
            const float4 p1 = __ldcg((const float4*)&g_P[j][b][d0 + 4]);
            cre[0] += p0.x; cre[1] += p0.y; cre[2] += p0.z; cre[3] += p0.w;
            cre[4] += p1.x; cre[5] += p1.y; cre[6] += p1.z; cre[7] += p1.w;
        }
        const float4 bd0 = *(const float4*)&bdt[d0];
        const float4 bd1 = *(const float4*)&bdt[d0 + 4];
        cre[0]+=bd0.x; cre[1]+=bd0.y; cre[2]+=bd0.z; cre[3]+=bd0.w;
        cre[4]+=bd1.x; cre[5]+=bd1.y; cre[6]+=bd1.z; cre[7]+=bd1.w;
    }

    __syncthreads();
    load_w(smp, Wdt, 0, k0, n0, tid);
    grid_barrier();

    for (int t = 0; t < TLEN; ++t) {
        float ev[8];
        if (t < TLEN - 1) {
            const int tkn = tok[(size_t)b * TLEN + t + 1];
            const float4 e0 = *(const float4*)&emb[(size_t)tkn * DIM + d0];
            const float4 e1 = *(const float4*)&emb[(size_t)tkn * DIM + d0 + 4];
            ev[0]=e0.x; ev[1]=e0.y; ev[2]=e0.z; ev[3]=e0.w;
            ev[4]=e1.x; ev[5]=e1.y; ev[6]=e1.z; ev[7]=e1.w;
        }

        gemm_step_mma(smp, base, &g_Uhi[0][0], &g_Ulo[0][0], m0, k0, n0, kc, tid);
        grid_barrier();

        float y[8];
        #pragma unroll
        for (int j = 0; j < 8; ++j) y[j] = cre[j] + ur[j];
        #pragma unroll
        for (int j = 0; j < NK; ++j) {
            const float4 p0 = __ldcg((const float4*)&g_P[j][b][d0]);
            const float4 p1 = __ldcg((const float4*)&g_P[j][b][d0 + 4]);
            y[0] += p0.x; y[1] += p0.y; y[2] += p0.z; y[3] += p0.w;
            y[4] += p1.x; y[5] += p1.y; y[6] += p1.z; y[7] += p1.w;
        }

        float s1 = 0.f, s2 = 0.f;
        #pragma unroll
        for (int j = 0; j < 8; ++j) { s1 += y[j]; s2 += y[j] * y[j]; }
        #pragma unroll
        for (int o = 16; o; o >>= 1) {
            s1 += __shfl_xor_sync(0xffffffffu, s1, o);
            s2 += __shfl_xor_sync(0xffffffffu, s2, o);
        }
        if ((tid & 31) == 0) { red[row_sel][0][wr] = s1; red[row_sel][1][wr] = s2; }
        __syncthreads();
        float t1 = 0.f, t2 = 0.f;
        #pragma unroll
        for (int j = 0; j < 4; ++j) {
            t1 += red[row_sel][0][j];
            t2 += red[row_sel][1][j];
        }
        __syncthreads();

        const float mean = t1 * (1.f / DIM);
        const float var  = t2 * (1.f / DIM) - mean * mean;
        const float rstd = rsqrtf(var + 1e-5f);

        float sv[8];
        #pragma unroll
        for (int j = 0; j < 8; ++j)
            sv[j] = (y[j] - mean) * rstd * gm[j] + bt[j];

        if (t < TLEN - 1) {
            float un[8];
            #pragma unroll
            for (int j = 0; j < 8; ++j) { un[j] = sv[j] + ev[j]; ur[j] = un[j]; }
            split_store8(&g_Uhi[b][d0], &g_Ulo[b][d0], un);
        } else {
            *(float4*)&zout[(size_t)b * DIM + d0] =
                make_float4(sv[0], sv[1], sv[2], sv[3]);
            *(float4*)&zout[(size_t)b * DIM + d0 + 4] =
                make_float4(sv[4], sv[5], sv[6], sv[7]);
            // z splits for the tensor-core logits kernel (U buffers are dead now)
            split_store8(&g_Uhi[b][d0], &g_Ulo[b][d0], sv);
        }
        grid_barrier();
    }
}

// ---------------------------------------------------------------------------
// Tensor-core logits: L[b][v] = sum_d z[b][d]*Wv[d][v] + bv[v]
// grid (250 v-tiles x 4 m-blocks); per CTA M=64 x N=128 x K=1024 (8 chunks).
// Same fragment idioms/strides family as the scan GEMM.
// ---------------------------------------------------------------------------
__global__ __launch_bounds__(256) void logits_mma_kernel(
    const float* __restrict__ Wv, const float* __restrict__ bv,
    float* __restrict__ L)
{
    extern __shared__ char smp[];
    const uint32_t base = smem_u32(smp);
    const int tid = threadIdx.x;
    const int v0 = blockIdx.x * 128;
    const int m0 = blockIdx.y * 64;
    const int lane = tid & 31, wid = tid >> 5;
    const int mw = wid & 3, nw = wid >> 2;

    float acc[8][4];
    #pragma unroll
    for (int nt = 0; nt < 8; ++nt)
        #pragma unroll
        for (int q = 0; q < 4; ++q) acc[nt][q] = 0.f;

    const uint32_t bb = base + LG_B;
    const uint32_t ab = base + LG_A;

    for (int c = 0; c < 8; ++c) {
        const int kg = c * 128;
        // A chunk via cp.async from z splits: 64 rows x 256B x 2 splits
        #pragma unroll
        for (int t = 0; t < 8; ++t) {
            const int i  = tid + t * 256;     // 0..2047
            const int sp = i >> 10;
            const int r  = (i >> 4) & 63;
            const int cc = i & 15;
            const __nv_bfloat16* src =
                (sp ? &g_Ulo[0][0] : &g_Uhi[0][0]) + (size_t)(m0 + r) * DIM + kg + cc * 8;
            cp_async16(ab + (uint32_t)sp * LG_ASPL + (uint32_t)r * LG_STR + (uint32_t)cc * 16u, src);
        }
        CP_COMMIT();
        // B chunk: Wv[kg+k][v0+n] fp32 -> hi/lo smem [128 k][128 n] stride 272
        for (int i = tid; i < 128 * 128; i += 256) {
            const int k = i >> 7;
            const int n = i & 127;
            const float v = Wv[(size_t)(kg + k) * VOCAB + v0 + n];
            const __nv_bfloat16 hi = __float2bfloat16(v);
            const __nv_bfloat16 lo = __float2bfloat16(v - __bfloat162float(hi));
            *(__nv_bfloat16*)(smp + LG_B + (uint32_t)k * LG_STR + (uint32_t)n * 2u) = hi;
            *(__nv_bfloat16*)(smp + LG_B + LG_BSPL + (uint32_t)k * LG_STR + (uint32_t)n * 2u) = lo;
        }
        CP_WAIT(0);
        __syncthreads();

        #pragma unroll
        for (int ks = 0; ks < 8; ++ks) {
            const uint32_t arow = (uint32_t)(mw * 16 + (lane & 15));
            const uint32_t acol = (uint32_t)(ks * 32 + (lane >> 4) * 16);
            uint32_t ah[4], al[4];
            {
                const uint32_t off = arow * LG_STR + acol;
                ldm_x4(ah, ab + off);
                ldm_x4(al, ab + LG_ASPL + off);
            }
            const uint32_t krow_b = (uint32_t)(ks * 16 + (lane & 15));
            #pragma unroll
            for (int g = 0; g < 2; ++g) {
                uint32_t bh[4][2], bl[4][2];
                #pragma unroll
                for (int j = 0; j < 4; ++j) {
                    const uint32_t nb = (uint32_t)(nw * 128 + (g * 4 + j) * 16);
                    ldm_x2_t(bh[j], bb + 0u      + krow_b * LG_STR + nb);
                    ldm_x2_t(bl[j], bb + LG_BSPL + krow_b * LG_STR + nb);
                }
                #pragma unroll
                for (int j = 0; j < 4; ++j) {
                    float* a = acc[g * 4 + j];
                    mma_bf16(a, ah, bh[j]);
                    mma_bf16(a, ah, bl[j]);
                    mma_bf16(a, al, bh[j]);
                }
            }
        }
        __syncthreads();
    }

    // epilogue: + bv, store
    const int r4 = lane >> 2, c2 = (lane & 3) * 2;
    #pragma unroll
    for (int nt = 0; nt < 8; ++nt) {
        const int r0 = m0 + mw * 16 + r4;
        const int cc = v0 + nw * 64 + nt * 8 + c2;
        const float2 bvv = *(const float2*)&bv[cc];
        *(float2*)&L[(size_t)r0 * VOCAB + cc] =
            make_float2(acc[nt][0] + bvv.x, acc[nt][1] + bvv.y);
        *(float2*)&L[(size_t)(r0 + 8) * VOCAB + cc] =
            make_float2(acc[nt][2] + bvv.x, acc[nt][3] + bvv.y);
    }
}

// ---------------------------------------------------------------------------
// In-place log_softmax over each row of L [BATCH][VOCAB]
// ---------------------------------------------------------------------------
__global__ __launch_bounds__(256) void logsoftmax_kernel(float* __restrict__ L)
{
    const int b   = blockIdx.x;
    const int tid = threadIdx.x;
    float* row = L + (size_t)b * VOCAB;
    __shared__ float red[8];

    float m = -1e30f;
    for (int i = tid * 4; i < VOCAB; i += 1024) {
        const float4 v = *(const float4*)&row[i];
        m = fmaxf(m, fmaxf(fmaxf(v.x, v.y), fmaxf(v.z, v.w)));
    }
    #pragma unroll
    for (int o = 16; o; o >>= 1) m = fmaxf(m, __shfl_xor_sync(0xffffffffu, m, o));
    if ((tid & 31) == 0) red[tid >> 5] = m;
    __syncthreads();
    float M = red[0];
    #pragma unroll
    for (int j = 1; j < 8; ++j) M = fmaxf(M, red[j]);
    __syncthreads();

    float s = 0.f;
    for (int i = tid * 4; i < VOCAB; i += 1024) {
        const float4 v = *(const float4*)&row[i];
        s += expf(v.x - M) + expf(v.y - M) + expf(v.z - M) + expf(v.w - M);
    }
    #pragma unroll
    for (int o = 16; o; o >>= 1) s += __shfl_xor_sync(0xffffffffu, s, o);
    if ((tid & 31) == 0) red[tid >> 5] = s;
    __syncthreads();
    float S = 0.f;
    #pragma unroll
    for (int j = 0; j < 8; ++j) S += red[j];
    const float lse = M + logf(S);

    for (int i = tid * 4; i < VOCAB; i += 1024) {
        float4 v = *(const float4*)&row[i];
        v.x -= lse; v.y -= lse; v.z -= lse; v.w -= lse;
        *(float4*)&row[i] = v;
    }
}

// ---------------------------------------------------------------------------
// kernel_launch — 3 graph nodes
// ---------------------------------------------------------------------------
extern "C" void kernel_launch(void* const* d_in, const int* in_sizes, int n_in,
                              void* d_out, int out_size)
{
    const float* hidden = (const float*)d_in[0];
    const int*   tok    = (const int*)  d_in[1];
    const float* emb    = (const float*)d_in[2];
    const float* Wdt    = (const float*)d_in[3];
    const float* bdt    = (const float*)d_in[4];
    const float* gamma  = (const float*)d_in[5];
    const float* beta   = (const float*)d_in[6];
    const float* Wv     = (const float*)d_in[7];
    const float* bv     = (const float*)d_in[8];

    float* zout = (float*)d_out;
    float* yout = zout + (size_t)BATCH * DIM;

    cudaFuncSetAttribute(rnn_persistent,
                         cudaFuncAttributeMaxDynamicSharedMemorySize, SMEM_BYTES);
    cudaFuncSetAttribute(logits_mma_kernel,
                         cudaFuncAttributeMaxDynamicSharedMemorySize, LG_SMEM);

    rnn_persistent<<<NCTA, 256, SMEM_BYTES>>>(hidden, tok, emb, Wdt, bdt, gamma, beta, zout);
    logits_mma_kernel<<<dim3(VOCAB / 128, 4), 256, LG_SMEM>>>(Wv, bv, yout);
    logsoftmax_kernel<<<BATCH, 256>>>(yout);
}

// round 16
// speedup vs baseline: 1.0770x; 1.0770x over previous
#include <cuda_runtime.h>
#include <cuda_bf16.h>
#include <math.h>
#include <stdint.h>

// Problem constants
#define BATCH 256
#define TLEN  512
#define DIM   1024
#define VOCAB 32000

// Persistent tiling: 128 CTAs (1/SM);
//   bid -> mb = bid&3 (64-row block), nc = (bid>>2)&7 (128-col tile), kc = bid>>5 (K=256 slab)
#define NK 4
#define KT 256
#define NT 128
#define NCTA 128

// SMEM layout (scan):
#define SM_W    0
#define W_SPL   69632u
#define WSTRIDE 272u
#define SM_A    139264
#define ASPL    33792u
#define ASTRIDE 528u
#define SMEM_BYTES (139264 + 67584)   // 206848

// SMEM layout (logits): B chunk [2 spl][128 k][136] stride 272; A chunk [2 spl][64 m][136]
#define LG_B     0
#define LG_BSPL  34816u
#define LG_A     69632
#define LG_ASPL  17408u
#define LG_STR   272u
#define LG_SMEM  (69632 + 34816)      // 104448

// ---------------------------------------------------------------------------
// Device scratch (static — no cudaMalloc allowed)
// ---------------------------------------------------------------------------
__device__ float         g_P[NK][BATCH][DIM];     // partial sums
__device__ __nv_bfloat16 g_Uhi[BATCH][DIM], g_Ulo[BATCH][DIM];  // u splits; z splits after scan
__device__ __nv_bfloat16 g_Hhi[BATCH][DIM], g_Hlo[BATCH][DIM];
__device__ __nv_bfloat16 g_Wvhi[(size_t)DIM * VOCAB];   // 64 MB bf16 split of Wv
__device__ __nv_bfloat16 g_Wvlo[(size_t)DIM * VOCAB];   // 64 MB
__device__ unsigned g_bar_arrive = 0;
__device__ unsigned g_bar_gen    = 0;

// ---------------------------------------------------------------------------
// PTX helpers
// ---------------------------------------------------------------------------
__device__ __forceinline__ uint32_t smem_u32(const void* p) {
    uint32_t a;
    asm("{ .reg .u64 t; cvta.to.shared.u64 t, %1; cvt.u32.u64 %0, t; }" : "=r"(a) : "l"(p));
    return a;
}
__device__ __forceinline__ void cp_async16(uint32_t dst, const void* src) {
    asm volatile("cp.async.cg.shared.global [%0], [%1], 16;" :: "r"(dst), "l"(src) : "memory");
}
#define CP_COMMIT() asm volatile("cp.async.commit_group;" ::: "memory")
#define CP_WAIT(n)  asm volatile("cp.async.wait_group %0;" :: "n"(n) : "memory")

__device__ __forceinline__ void ldm_x4(uint32_t* r, uint32_t addr) {
    asm volatile("ldmatrix.sync.aligned.m8n8.x4.shared.b16 {%0,%1,%2,%3}, [%4];"
                 : "=r"(r[0]), "=r"(r[1]), "=r"(r[2]), "=r"(r[3]) : "r"(addr));
}
__device__ __forceinline__ void ldm_x2_t(uint32_t* r, uint32_t addr) {
    asm volatile("ldmatrix.sync.aligned.m8n8.x2.trans.shared.b16 {%0,%1}, [%2];"
                 : "=r"(r[0]), "=r"(r[1]) : "r"(addr));
}
__device__ __forceinline__ void mma_bf16(float* c, const uint32_t* a, const uint32_t* b) {
    asm volatile(
        "mma.sync.aligned.m16n8k16.row.col.f32.bf16.bf16.f32 "
        "{%0,%1,%2,%3}, {%4,%5,%6,%7}, {%8,%9}, {%0,%1,%2,%3};"
        : "+f"(c[0]), "+f"(c[1]), "+f"(c[2]), "+f"(c[3])
        : "r"(a[0]), "r"(a[1]), "r"(a[2]), "r"(a[3]), "r"(b[0]), "r"(b[1]));
}
__device__ __forceinline__ uint32_t pack_bf16x2(float a, float b) {
    const __nv_bfloat16 ba = __float2bfloat16(a);
    const __nv_bfloat16 bb = __float2bfloat16(b);
    return (uint32_t)__bfloat16_as_ushort(ba) | ((uint32_t)__bfloat16_as_ushort(bb) << 16);
}
__device__ __forceinline__ void split_store8(__nv_bfloat16* hp, __nv_bfloat16* lp,
                                             const float* v)
{
    uint32_t h[4], l[4];
    #pragma unroll
    for (int q = 0; q < 4; ++q) {
        const float a = v[2*q], b = v[2*q+1];
        h[q] = pack_bf16x2(a, b);
        const float la = a - __bfloat162float(__float2bfloat16(a));
        const float lb = b - __bfloat162float(__float2bfloat16(b));
        l[q] = pack_bf16x2(la, lb);
    }
    __stcg((uint4*)hp, make_uint4(h[0], h[1], h[2], h[3]));
    __stcg((uint4*)lp, make_uint4(l[0], l[1], l[2], l[3]));
}

// ---------------------------------------------------------------------------
// Grid-wide barrier (R11/R14-proven)
// ---------------------------------------------------------------------------
__device__ __forceinline__ void grid_barrier()
{
    __threadfence();
    __syncthreads();
    if (threadIdx.x == 0) {
        unsigned gen = *(volatile unsigned*)&g_bar_gen;
        if (atomicAdd(&g_bar_arrive, 1u) == NCTA - 1u) {
            atomicExch(&g_bar_arrive, 0u);
            __threadfence();
            atomicAdd(&g_bar_gen, 1u);
        } else {
            while (*(volatile unsigned*)&g_bar_gen == gen) { }
        }
        __threadfence();
    }
    __syncthreads();
}

// ---------------------------------------------------------------------------
// W tile load: fp32 Wdt -> smem bf16 hi/lo, [256 k][128 n] stride 272B
// ---------------------------------------------------------------------------
__device__ __forceinline__ void load_w(char* smp, const float* __restrict__ Wdt,
                                       int half, int k0, int n0, int tid)
{
    for (int i = tid; i < KT * NT; i += 256) {
        const int k = i >> 7;
        const int n = i & 127;
        const float v = Wdt[(size_t)(half * DIM + k0 + k) * DIM + n0 + n];
        const __nv_bfloat16 hi = __float2bfloat16(v);
        const __nv_bfloat16 lo = __float2bfloat16(v - __bfloat162float(hi));
        *(__nv_bfloat16*)(smp + SM_W + (uint32_t)k * WSTRIDE + (uint32_t)n * 2u) = hi;
        *(__nv_bfloat16*)(smp + SM_W + W_SPL + (uint32_t)k * WSTRIDE + (uint32_t)n * 2u) = lo;
    }
}

// cp.async one K=128 half of A (hi+lo): 64 rows x 256B x 2 splits = 2048 x 16B
__device__ __forceinline__ void issue_half(uint32_t sa_base,
    const __nv_bfloat16* __restrict__ srchi, const __nv_bfloat16* __restrict__ srclo,
    int m0, int kglob, uint32_t dcol, int tid)
{
    #pragma unroll
    for (int t = 0; t < 8; ++t) {
        const int i  = tid + t * 256;
        const int sp = i >> 10;
        const int r  = (i >> 4) & 63;
        const int c  = i & 15;
        const __nv_bfloat16* src =
            (sp ? srclo : srchi) + (size_t)(m0 + r) * DIM + kglob + c * 8;
        const uint32_t dst = sa_base + (uint32_t)sp * ASPL
                           + (uint32_t)r * ASTRIDE + dcol + (uint32_t)c * 16u;
        cp_async16(dst, src);
    }
    CP_COMMIT();
}

// ---------------------------------------------------------------------------
// Compute 8 ksteps (one K=128 half): warp (mw = wid&3, nw = wid>>2)
// ---------------------------------------------------------------------------
__device__ __forceinline__ void compute_half(uint32_t abase, uint32_t wbase, int ks0,
                                             float acc[8][4], int lane, int mw, int nw)
{
    #pragma unroll
    for (int ks = ks0; ks < ks0 + 8; ++ks) {
        const uint32_t arow = (uint32_t)(mw * 16 + (lane & 15));
        const uint32_t acol = (uint32_t)(ks * 32 + (lane >> 4) * 16);
        uint32_t ah[4], al[4];
        {
            const uint32_t off = arow * ASTRIDE + acol;
            ldm_x4(ah, abase + off);
            ldm_x4(al, abase + ASPL + off);
        }
        const uint32_t krow_b = (uint32_t)(ks * 16 + (lane & 15));
        #pragma unroll
        for (int g = 0; g < 2; ++g) {
            uint32_t bh[4][2], bl[4][2];
            #pragma unroll
            for (int j = 0; j < 4; ++j) {
                const uint32_t nb = (uint32_t)(nw * 128 + (g * 4 + j) * 16);
                ldm_x2_t(bh[j], wbase + 0u    + krow_b * WSTRIDE + nb);
                ldm_x2_t(bl[j], wbase + W_SPL + krow_b * WSTRIDE + nb);
            }
            #pragma unroll
            for (int j = 0; j < 4; ++j) {
                float* a = acc[g * 4 + j];
                mma_bf16(a, ah, bh[j]);
                mma_bf16(a, ah, bl[j]);
                mma_bf16(a, al, bh[j]);
            }
        }
    }
}

// ---------------------------------------------------------------------------
// One full step GEMM: P[kc][m0..m0+63][n0..n0+127] over K [k0, k0+256)
// ---------------------------------------------------------------------------
__device__ __forceinline__ void gemm_step_mma(char* smp, uint32_t base,
    const __nv_bfloat16* __restrict__ srchi, const __nv_bfloat16* __restrict__ srclo,
    int m0, int k0, int n0, int kc, int tid)
{
    const int lane = tid & 31, wid = tid >> 5;
    const int mw = wid & 3, nw = wid >> 2;
    float acc[8][4];
    #pragma unroll
    for (int nt = 0; nt < 8; ++nt)
        #pragma unroll
        for (int q = 0; q < 4; ++q) acc[nt][q] = 0.f;

    const uint32_t ab = base + SM_A;
    const uint32_t wb = base + SM_W;

    issue_half(ab, srchi, srclo, m0, k0 + 0,   0u,   tid);
    issue_half(ab, srchi, srclo, m0, k0 + 128, 256u, tid);

    CP_WAIT(1); __syncthreads();
    compute_half(ab, wb, 0, acc, lane, mw, nw);
    CP_WAIT(0); __syncthreads();
    compute_half(ab, wb, 8, acc, lane, mw, nw);

    const int r4 = lane >> 2, c2 = (lane & 3) * 2;
    #pragma unroll
    for (int nt = 0; nt < 8; ++nt) {
        const int r0 = m0 + mw * 16 + r4;
        const int cc = n0 + nw * 64 + nt * 8 + c2;
        __stcg((float2*)&g_P[kc][r0][cc],     make_float2(acc[nt][0], acc[nt][1]));
        __stcg((float2*)&g_P[kc][r0 + 8][cc], make_float2(acc[nt][2], acc[nt][3]));
    }
}

// ---------------------------------------------------------------------------
// Persistent scan kernel (R14-proven; z splits stored at last step)
// ---------------------------------------------------------------------------
__global__ __launch_bounds__(256) void rnn_persistent(
    const float* __restrict__ hidden, const int* __restrict__ tok,
    const float* __restrict__ emb,    const float* __restrict__ Wdt,
    const float* __restrict__ bdt,    const float* __restrict__ gamma,
    const float* __restrict__ beta,   float* __restrict__ zout)
{
    extern __shared__ char smp[];
    const uint32_t base = smem_u32(smp);
    __shared__ float red[2][2][4];

    const int tid = threadIdx.x;
    const int bid = blockIdx.x;
    const int mb = bid & 3, nc = (bid >> 2) & 7, kc = bid >> 5;
    const int m0 = mb * 64, n0 = nc * NT, k0 = kc * KT;

    const int row_sel = tid >> 7;
    const int b  = bid * 2 + row_sel;
    const int lt = tid & 127;
    const int d0 = lt * 8;
    const int wr = (tid >> 5) & 3;

    float ur[8], gm[8], bt[8];
    {
        const int tk0 = tok[(size_t)b * TLEN];
        float hv[8];
        const float4 h0 = *(const float4*)&hidden[(size_t)b * DIM + d0];
        const float4 h1 = *(const float4*)&hidden[(size_t)b * DIM + d0 + 4];
        hv[0]=h0.x; hv[1]=h0.y; hv[2]=h0.z; hv[3]=h0.w;
        hv[4]=h1.x; hv[5]=h1.y; hv[6]=h1.z; hv[7]=h1.w;
        const float4 u0 = *(const float4*)&emb[(size_t)tk0 * DIM + d0];
        const float4 u1 = *(const float4*)&emb[(size_t)tk0 * DIM + d0 + 4];
        ur[0]=u0.x; ur[1]=u0.y; ur[2]=u0.z; ur[3]=u0.w;
        ur[4]=u1.x; ur[5]=u1.y; ur[6]=u1.z; ur[7]=u1.w;
        split_store8(&g_Hhi[b][d0], &g_Hlo[b][d0], hv);
        split_store8(&g_Uhi[b][d0], &g_Ulo[b][d0], ur);
        const float4 g0 = *(const float4*)&gamma[d0];
        const float4 g1 = *(const float4*)&gamma[d0 + 4];
        gm[0]=g0.x; gm[1]=g0.y; gm[2]=g0.z; gm[3]=g0.w;
        gm[4]=g1.x; gm[5]=g1.y; gm[6]=g1.z; gm[7]=g1.w;
        const float4 b0 = *(const float4*)&beta[d0];
        const float4 b1 = *(const float4*)&beta[d0 + 4];
        bt[0]=b0.x; bt[1]=b0.y; bt[2]=b0.z; bt[3]=b0.w;
        bt[4]=b1.x; bt[5]=b1.y; bt[6]=b1.z; bt[7]=b1.w;
    }

    load_w(smp, Wdt, 1, k0, n0, tid);
    grid_barrier();
    gemm_step_mma(smp, base, &g_Hhi[0][0], &g_Hlo[0][0], m0, k0, n0, kc, tid);
    grid_barrier();

    float cre[8];
    {
        #pragma unroll
        for (int j = 0; j < 8; ++j) cre[j] = 0.f;
        #pragma unroll
        for (int j = 0; j < NK; ++j) {
            const float4 p0 = __ldcg((const float4*)&g_P[j][b][d0]);
            const float4 p1 = __ldcg((const float4*)&g_P[j][b][d0 + 4]);
            cre[0] += p0.x; cre[1] += p0.y; cre[2] += p0.z; cre[3] += p0.w;
            cre[4] += p1.x; cre[5] += p1.y; cre[6] += p1.z; cre[7] += p1.w;
        }
        const float4 bd0 = *(const float4*)&bdt[d0];
        const float4 bd1 = *(const float4*)&bdt[d0 + 4];
        cre[0]+=bd0.x; cre[1]+=bd0.y; cre[2]+=bd0.z; cre[3]+=bd0.w;
        cre[4]+=bd1.x; cre[5]+=bd1.y; cre[6]+=bd1.z; cre[7]+=bd1.w;
    }

    __syncthreads();
    load_w(smp, Wdt, 0, k0, n0, tid);
    grid_barrier();

    for (int t = 0; t < TLEN; ++t) {
        float ev[8];
        if (t < TLEN - 1) {
            const int tkn = tok[(size_t)b * TLEN + t + 1];
            const float4 e0 = *(const float4*)&emb[(size_t)tkn * DIM + d0];
            const float4 e1 = *(const float4*)&emb[(size_t)tkn * DIM + d0 + 4];
            ev[0]=e0.x; ev[1]=e0.y; ev[2]=e0.z; ev[3]=e0.w;
            ev[4]=e1.x; ev[5]=e1.y; ev[6]=e1.z; ev[7]=e1.w;
        }

        gemm_step_mma(smp, base, &g_Uhi[0][0], &g_Ulo[0][0], m0, k0, n0, kc, tid);
        grid_barrier();

        float y[8];
        #pragma unroll
        for (int j = 0; j < 8; ++j) y[j] = cre[j] + ur[j];
        #pragma unroll
        for (int j = 0; j < NK; ++j) {
            const float4 p0 = __ldcg((const float4*)&g_P[j][b][d0]);
            const float4 p1 = __ldcg((const float4*)&g_P[j][b][d0 + 4]);
            y[0] += p0.x; y[1] += p0.y; y[2] += p0.z; y[3] += p0.w;
            y[4] += p1.x; y[5] += p1.y; y[6] += p1.z; y[7] += p1.w;
        }

        float s1 = 0.f, s2 = 0.f;
        #pragma unroll
        for (int j = 0; j < 8; ++j) { s1 += y[j]; s2 += y[j] * y[j]; }
        #pragma unroll
        for (int o = 16; o; o >>= 1) {
            s1 += __shfl_xor_sync(0xffffffffu, s1, o);
            s2 += __shfl_xor_sync(0xffffffffu, s2, o);
        }
        if ((tid & 31) == 0) { red[row_sel][0][wr] = s1; red[row_sel][1][wr] = s2; }
        __syncthreads();
        float t1 = 0.f, t2 = 0.f;
        #pragma unroll
        for (int j = 0; j < 4; ++j) {
            t1 += red[row_sel][0][j];
            t2 += red[row_sel][1][j];
        }
        __syncthreads();

        const float mean = t1 * (1.f / DIM);
        const float var  = t2 * (1.f / DIM) - mean * mean;
        const float rstd = rsqrtf(var + 1e-5f);

        float sv[8];
        #pragma unroll
        for (int j = 0; j < 8; ++j)
            sv[j] = (y[j] - mean) * rstd * gm[j] + bt[j];

        if (t < TLEN - 1) {
            float un[8];
            #pragma unroll
            for (int j = 0; j < 8; ++j) { un[j] = sv[j] + ev[j]; ur[j] = un[j]; }
            split_store8(&g_Uhi[b][d0], &g_Ulo[b][d0], un);
        } else {
            *(float4*)&zout[(size_t)b * DIM + d0] =
                make_float4(sv[0], sv[1], sv[2], sv[3]);
            *(float4*)&zout[(size_t)b * DIM + d0 + 4] =
                make_float4(sv[4], sv[5], sv[6], sv[7]);
            split_store8(&g_Uhi[b][d0], &g_Ulo[b][d0], sv);  // z splits for logits
        }
        grid_barrier();
    }
}

// ---------------------------------------------------------------------------
// Wv prep: fp32 -> bf16 hi/lo split (flat copy, bandwidth-bound)
// grid 32000 x 256 threads, one float4 per thread
// ---------------------------------------------------------------------------
__global__ __launch_bounds__(256) void prep_wv(const float* __restrict__ Wv)
{
    const size_t idx = ((size_t)blockIdx.x * 256 + threadIdx.x) * 4;
    const float4 v = *(const float4*)&Wv[idx];
    const uint32_t h0 = pack_bf16x2(v.x, v.y);
    const uint32_t h1 = pack_bf16x2(v.z, v.w);
    const float lx = v.x - __bfloat162float(__float2bfloat16(v.x));
    const float ly = v.y - __bfloat162float(__float2bfloat16(v.y));
    const float lz = v.z - __bfloat162float(__float2bfloat16(v.z));
    const float lw = v.w - __bfloat162float(__float2bfloat16(v.w));
    __stcg((uint2*)&g_Wvhi[idx], make_uint2(h0, h1));
    __stcg((uint2*)&g_Wvlo[idx], make_uint2(pack_bf16x2(lx, ly), pack_bf16x2(lz, lw)));
}

// ---------------------------------------------------------------------------
// Tensor-core logits: L[b][v] = sum_d z[b][d]*Wv[d][v] + bv[v]
// grid (4 m-blocks, 250 v-tiles) — m fastest so v-tile peers share L2.
// All operands bf16 via cp.async; per CTA M=64 x N=128 x K=1024 (8 chunks).
// ---------------------------------------------------------------------------
__global__ __launch_bounds__(256) void logits_mma_kernel(
    const float* __restrict__ bv, float* __restrict__ L)
{
    extern __shared__ char smp[];
    const uint32_t base = smem_u32(smp);
    const int tid = threadIdx.x;
    const int m0 = blockIdx.x * 64;
    const int v0 = blockIdx.y * 128;
    const int lane = tid & 31, wid = tid >> 5;
    const int mw = wid & 3, nw = wid >> 2;

    float acc[8][4];
    #pragma unroll
    for (int nt = 0; nt < 8; ++nt)
        #pragma unroll
        for (int q = 0; q < 4; ++q) acc[nt][q] = 0.f;

    const uint32_t bb = base + LG_B;
    const uint32_t ab = base + LG_A;

    // issue chunk 0
    {
        const int kg = 0;
        #pragma unroll
        for (int t = 0; t < 8; ++t) {      // A: 2048 x 16B
            const int i  = tid + t * 256;
            const int sp = i >> 10;
            const int r  = (i >> 4) & 63;
            const int cc = i & 15;
            const __nv_bfloat16* src =
                (sp ? &g_Ulo[0][0] : &g_Uhi[0][0]) + (size_t)(m0 + r) * DIM + kg + cc * 8;
            cp_async16(ab + (uint32_t)sp * LG_ASPL + (uint32_t)r * LG_STR + (uint32_t)cc * 16u, src);
        }
        #pragma unroll
        for (int t = 0; t < 16; ++t) {     // B: 4096 x 16B
            const int i  = tid + t * 256;
            const int sp = i >> 11;
            const int r  = (i >> 4) & 127;
            const int cc = i & 15;
            const __nv_bfloat16* src =
                (sp ? g_Wvlo : g_Wvhi) + (size_t)(kg + r) * VOCAB + v0 + cc * 8;
            cp_async16(bb + (uint32_t)sp * LG_BSPL + (uint32_t)r * LG_STR + (uint32_t)cc * 16u, src);
        }
        CP_COMMIT();
    }

    for (int c = 0; c < 8; ++c) {
        CP_WAIT(0);
        __syncthreads();

        #pragma unroll
        for (int ks = 0; ks < 8; ++ks) {
            const uint32_t arow = (uint32_t)(mw * 16 + (lane & 15));
            const uint32_t acol = (uint32_t)(ks * 32 + (lane >> 4) * 16);
            uint32_t ah[4], al[4];
            {
                const uint32_t off = arow * LG_STR + acol;
                ldm_x4(ah, ab + off);
                ldm_x4(al, ab + LG_ASPL + off);
            }
            const uint32_t krow_b = (uint32_t)(ks * 16 + (lane & 15));
            #pragma unroll
            for (int g = 0; g < 2; ++g) {
                uint32_t bh[4][2], bl[4][2];
                #pragma unroll
                for (int j = 0; j < 4; ++j) {
                    const uint32_t nb = (uint32_t)(nw * 128 + (g * 4 + j) * 16);
                    ldm_x2_t(bh[j], bb + 0u      + krow_b * LG_STR + nb);
                    ldm_x2_t(bl[j], bb + LG_BSPL + krow_b * LG_STR + nb);
                }
                #pragma unroll
                for (int j = 0; j < 4; ++j) {
                    float* a = acc[g * 4 + j];
                    mma_bf16(a, ah, bh[j]);
                    mma_bf16(a, ah, bl[j]);
                    mma_bf16(a, al, bh[j]);
                }
            }
        }
        __syncthreads();

        // issue next chunk
        if (c < 7) {
            const int kg = (c + 1) * 128;
            #pragma unroll
            for (int t = 0; t < 8; ++t) {
                const int i  = tid + t * 256;
                const int sp = i >> 10;
                const int r  = (i >> 4) & 63;
                const int cc = i & 15;
                const __nv_bfloat16* src =
                    (sp ? &g_Ulo[0][0] : &g_Uhi[0][0]) + (size_t)(m0 + r) * DIM + kg + cc * 8;
                cp_async16(ab + (uint32_t)sp * LG_ASPL + (uint32_t)r * LG_STR + (uint32_t)cc * 16u, src);
            }
            #pragma unroll
            for (int t = 0; t < 16; ++t) {
                const int i  = tid + t * 256;
                const int sp = i >> 11;
                const int r  = (i >> 4) & 127;
                const int cc = i & 15;
                const __nv_bfloat16* src =
                    (sp ? g_Wvlo : g_Wvhi) + (size_t)(kg + r) * VOCAB + v0 + cc * 8;
                cp_async16(bb + (uint32_t)sp * LG_BSPL + (uint32_t)r * LG_STR + (uint32_t)cc * 16u, src);
            }
            CP_COMMIT();
        }
    }

    const int r4 = lane >> 2, c2 = (lane & 3) * 2;
    #pragma unroll
    for (int nt = 0; nt < 8; ++nt) {
        const int r0 = m0 + mw * 16 + r4;
        const int cc = v0 + nw * 64 + nt * 8 + c2;
        const float2 bvv = *(const float2*)&bv[cc];
        *(float2*)&L[(size_t)r0 * VOCAB + cc] =
            make_float2(acc[nt][0] + bvv.x, acc[nt][1] + bvv.y);
        *(float2*)&L[(size_t)(r0 + 8) * VOCAB + cc] =
            make_float2(acc[nt][2] + bvv.x, acc[nt][3] + bvv.y);
    }
}

// ---------------------------------------------------------------------------
// In-place log_softmax over each row of L [BATCH][VOCAB]
// ---------------------------------------------------------------------------
__global__ __launch_bounds__(256) void logsoftmax_kernel(float* __restrict__ L)
{
    const int b   = blockIdx.x;
    const int tid = threadIdx.x;
    float* row = L + (size_t)b * VOCAB;
    __shared__ float red[8];

    float m = -1e30f;
    for (int i = tid * 4; i < VOCAB; i += 1024) {
        const float4 v = *(const float4*)&row[i];
        m = fmaxf(m, fmaxf(fmaxf(v.x, v.y), fmaxf(v.z, v.w)));
    }
    #pragma unroll
    for (int o = 16; o; o >>= 1) m = fmaxf(m, __shfl_xor_sync(0xffffffffu, m, o));
    if ((tid & 31) == 0) red[tid >> 5] = m;
    __syncthreads();
    float M = red[0];
    #pragma unroll
    for (int j = 1; j < 8; ++j) M = fmaxf(M, red[j]);
    __syncthreads();

    float s = 0.f;
    for (int i = tid * 4; i < VOCAB; i += 1024) {
        const float4 v = *(const float4*)&row[i];
        s += expf(v.x - M) + expf(v.y - M) + expf(v.z - M) + expf(v.w - M);
    }
    #pragma unroll
    for (int o = 16; o; o >>= 1) s += __shfl_xor_sync(0xffffffffu, s, o);
    if ((tid & 31) == 0) red[tid >> 5] = s;
    __syncthreads();
    float S = 0.f;
    #pragma unroll
    for (int j = 0; j < 8; ++j) S += red[j];
    const float lse = M + logf(S);

    for (int i = tid * 4; i < VOCAB; i += 1024) {
        float4 v = *(const float4*)&row[i];
        v.x -= lse; v.y -= lse; v.z -= lse; v.w -= lse;
        *(float4*)&row[i] = v;
    }
}

// ---------------------------------------------------------------------------
// kernel_launch — 4 graph nodes
// ---------------------------------------------------------------------------
extern "C" void kernel_launch(void* const* d_in, const int* in_sizes, int n_in,
                              void* d_out, int out_size)
{
    const float* hidden = (const float*)d_in[0];
    const int*   tok    = (const int*)  d_in[1];
    const float* emb    = (const float*)d_in[2];
    const float* Wdt    = (const float*)d_in[3];
    const float* bdt    = (const float*)d_in[4];
    const float* gamma  = (const float*)d_in[5];
    const float* beta   = (const float*)d_in[6];
    const float* Wv     = (const float*)d_in[7];
    const float* bv     = (const float*)d_in[8];

    float* zout = (float*)d_out;
    float* yout = zout + (size_t)BATCH * DIM;

    cudaFuncSetAttribute(rnn_persistent,
                         cudaFuncAttributeMaxDynamicSharedMemorySize, SMEM_BYTES);
    cudaFuncSetAttribute(logits_mma_kernel,
                         cudaFuncAttributeMaxDynamicSharedMemorySize, LG_SMEM);

    prep_wv<<<VOCAB, 256>>>(Wv);   // overlaps nothing but is bandwidth-bound (~50us)
    rnn_persistent<<<NCTA, 256, SMEM_BYTES>>>(hidden, tok, emb, Wdt, bdt, gamma, beta, zout);
    logits_mma_kernel<<<dim3(4, VOCAB / 128), 256, LG_SMEM>>>(bv, yout);
    logsoftmax_kernel<<<BATCH, 256>>>(yout);
}

// round 17
// speedup vs baseline: 1.0905x; 1.0125x over previous
#include <cuda_runtime.h>
#include <cuda_bf16.h>
#include <math.h>
#include <stdint.h>

// Problem constants
#define BATCH 256
#define TLEN  512
#define DIM   1024
#define VOCAB 32000

// Persistent tiling: 128 scan CTAs (1/SM) + extra CTAs for Wv conversion.
//   bid -> mb = bid&3 (64-row block), nc = (bid>>2)&7 (128-col tile), kc = bid>>5 (K=256 slab)
#define NK 4
#define KT 256
#define NT 128
#define NCTA 128
#define GRID_TOTAL 148        // 128 scan + up-to-20 converter CTAs

// SMEM layout (scan):
#define SM_W    0
#define W_SPL   69632u
#define WSTRIDE 272u
#define SM_A    139264
#define ASPL    33792u
#define ASTRIDE 528u
#define SMEM_BYTES (139264 + 67584)   // 206848

// SMEM layout (logits, double-buffered): per buf: B [2 spl][128 k][136] + A [2 spl][64 m][136]
#define LG_B     0
#define LG_BSPL  34816u
#define LG_A     69632
#define LG_ASPL  17408u
#define LG_STR   272u
#define LG_BUF   104448u
#define LG_SMEM  (2 * 104448)         // 208896

// ---------------------------------------------------------------------------
// Device scratch (static — no cudaMalloc allowed)
// ---------------------------------------------------------------------------
__device__ float         g_P[NK][BATCH][DIM];     // partial sums
__device__ __nv_bfloat16 g_Uhi[BATCH][DIM], g_Ulo[BATCH][DIM];  // u splits; z splits after scan
__device__ __nv_bfloat16 g_Hhi[BATCH][DIM], g_Hlo[BATCH][DIM];
__device__ __nv_bfloat16 g_Wvhi[(size_t)DIM * VOCAB];   // 64 MB bf16 split of Wv
__device__ __nv_bfloat16 g_Wvlo[(size_t)DIM * VOCAB];   // 64 MB
__device__ unsigned g_bar_arrive = 0;
__device__ unsigned g_bar_gen    = 0;

// ---------------------------------------------------------------------------
// PTX helpers
// ---------------------------------------------------------------------------
__device__ __forceinline__ uint32_t smem_u32(const void* p) {
    uint32_t a;
    asm("{ .reg .u64 t; cvta.to.shared.u64 t, %1; cvt.u32.u64 %0, t; }" : "=r"(a) : "l"(p));
    return a;
}
__device__ __forceinline__ void cp_async16(uint32_t dst, const void* src) {
    asm volatile("cp.async.cg.shared.global [%0], [%1], 16;" :: "r"(dst), "l"(src) : "memory");
}
#define CP_COMMIT() asm volatile("cp.async.commit_group;" ::: "memory")
#define CP_WAIT(n)  asm volatile("cp.async.wait_group %0;" :: "n"(n) : "memory")

__device__ __forceinline__ void ldm_x4(uint32_t* r, uint32_t addr) {
    asm volatile("ldmatrix.sync.aligned.m8n8.x4.shared.b16 {%0,%1,%2,%3}, [%4];"
                 : "=r"(r[0]), "=r"(r[1]), "=r"(r[2]), "=r"(r[3]) : "r"(addr));
}
__device__ __forceinline__ void ldm_x2_t(uint32_t* r, uint32_t addr) {
    asm volatile("ldmatrix.sync.aligned.m8n8.x2.trans.shared.b16 {%0,%1}, [%2];"
                 : "=r"(r[0]), "=r"(r[1]) : "r"(addr));
}
__device__ __forceinline__ void mma_bf16(float* c, const uint32_t* a, const uint32_t* b) {
    asm volatile(
        "mma.sync.aligned.m16n8k16.row.col.f32.bf16.bf16.f32 "
        "{%0,%1,%2,%3}, {%4,%5,%6,%7}, {%8,%9}, {%0,%1,%2,%3};"
        : "+f"(c[0]), "+f"(c[1]), "+f"(c[2]), "+f"(c[3])
        : "r"(a[0]), "r"(a[1]), "r"(a[2]), "r"(a[3]), "r"(b[0]), "r"(b[1]));
}
__device__ __forceinline__ uint32_t pack_bf16x2(float a, float b) {
    const __nv_bfloat16 ba = __float2bfloat16(a);
    const __nv_bfloat16 bb = __float2bfloat16(b);
    return (uint32_t)__bfloat16_as_ushort(ba) | ((uint32_t)__bfloat16_as_ushort(bb) << 16);
}
__device__ __forceinline__ void split_store8(__nv_bfloat16* hp, __nv_bfloat16* lp,
                                             const float* v)
{
    uint32_t h[4], l[4];
    #pragma unroll
    for (int q = 0; q < 4; ++q) {
        const float a = v[2*q], b = v[2*q+1];
        h[q] = pack_bf16x2(a, b);
        const float la = a - __bfloat162float(__float2bfloat16(a));
        const float lb = b - __bfloat162float(__float2bfloat16(b));
        l[q] = pack_bf16x2(la, lb);
    }
    __stcg((uint4*)hp, make_uint4(h[0], h[1], h[2], h[3]));
    __stcg((uint4*)lp, make_uint4(l[0], l[1], l[2], l[3]));
}

// ---------------------------------------------------------------------------
// Grid-wide barrier (R11/R14-proven; only the 128 scan CTAs participate)
// ---------------------------------------------------------------------------
__device__ __forceinline__ void grid_barrier()
{
    __threadfence();
    __syncthreads();
    if (threadIdx.x == 0) {
        unsigned gen = *(volatile unsigned*)&g_bar_gen;
        if (atomicAdd(&g_bar_arrive, 1u) == NCTA - 1u) {
            atomicExch(&g_bar_arrive, 0u);
            __threadfence();
            atomicAdd(&g_bar_gen, 1u);
        } else {
            while (*(volatile unsigned*)&g_bar_gen == gen) { }
        }
        __threadfence();
    }
    __syncthreads();
}

// ---------------------------------------------------------------------------
// W tile load: fp32 Wdt -> smem bf16 hi/lo, [256 k][128 n] stride 272B
// ---------------------------------------------------------------------------
__device__ __forceinline__ void load_w(char* smp, const float* __restrict__ Wdt,
                                       int half, int k0, int n0, int tid)
{
    for (int i = tid; i < KT * NT; i += 256) {
        const int k = i >> 7;
        const int n = i & 127;
        const float v = Wdt[(size_t)(half * DIM + k0 + k) * DIM + n0 + n];
        const __nv_bfloat16 hi = __float2bfloat16(v);
        const __nv_bfloat16 lo = __float2bfloat16(v - __bfloat162float(hi));
        *(__nv_bfloat16*)(smp + SM_W + (uint32_t)k * WSTRIDE + (uint32_t)n * 2u) = hi;
        *(__nv_bfloat16*)(smp + SM_W + W_SPL + (uint32_t)k * WSTRIDE + (uint32_t)n * 2u) = lo;
    }
}

// cp.async one K=128 half of A (hi+lo): 64 rows x 256B x 2 splits = 2048 x 16B
__device__ __forceinline__ void issue_half(uint32_t sa_base,
    const __nv_bfloat16* __restrict__ srchi, const __nv_bfloat16* __restrict__ srclo,
    int m0, int kglob, uint32_t dcol, int tid)
{
    #pragma unroll
    for (int t = 0; t < 8; ++t) {
        const int i  = tid + t * 256;
        const int sp = i >> 10;
        const int r  = (i >> 4) & 63;
        const int c  = i & 15;
        const __nv_bfloat16* src =
            (sp ? srclo : srchi) + (size_t)(m0 + r) * DIM + kglob + c * 8;
        const uint32_t dst = sa_base + (uint32_t)sp * ASPL
                           + (uint32_t)r * ASTRIDE + dcol + (uint32_t)c * 16u;
        cp_async16(dst, src);
    }
    CP_COMMIT();
}

// ---------------------------------------------------------------------------
// Compute 8 ksteps (one K=128 half): warp (mw = wid&3, nw = wid>>2)
// ---------------------------------------------------------------------------
__device__ __forceinline__ void compute_half(uint32_t abase, uint32_t wbase, int ks0,
                                             float acc[8][4], int lane, int mw, int nw)
{
    #pragma unroll
    for (int ks = ks0; ks < ks0 + 8; ++ks) {
        const uint32_t arow = (uint32_t)(mw * 16 + (lane & 15));
        const uint32_t acol = (uint32_t)(ks * 32 + (lane >> 4) * 16);
        uint32_t ah[4], al[4];
        {
            const uint32_t off = arow * ASTRIDE + acol;
            ldm_x4(ah, abase + off);
            ldm_x4(al, abase + ASPL + off);
        }
        const uint32_t krow_b = (uint32_t)(ks * 16 + (lane & 15));
        #pragma unroll
        for (int g = 0; g < 2; ++g) {
            uint32_t bh[4][2], bl[4][2];
            #pragma unroll
            for (int j = 0; j < 4; ++j) {
                const uint32_t nb = (uint32_t)(nw * 128 + (g * 4 + j) * 16);
                ldm_x2_t(bh[j], wbase + 0u    + krow_b * WSTRIDE + nb);
                ldm_x2_t(bl[j], wbase + W_SPL + krow_b * WSTRIDE + nb);
            }
            #pragma unroll
            for (int j = 0; j < 4; ++j) {
                float* a = acc[g * 4 + j];
                mma_bf16(a, ah, bh[j]);
                mma_bf16(a, ah, bl[j]);
                mma_bf16(a, al, bh[j]);
            }
        }
    }
}

// ---------------------------------------------------------------------------
// One full step GEMM: P[kc][m0..m0+63][n0..n0+127] over K [k0, k0+256)
// ---------------------------------------------------------------------------
__device__ __forceinline__ void gemm_step_mma(char* smp, uint32_t base,
    const __nv_bfloat16* __restrict__ srchi, const __nv_bfloat16* __restrict__ srclo,
    int m0, int k0, int n0, int kc, int tid)
{
    const int lane = tid & 31, wid = tid >> 5;
    const int mw = wid & 3, nw = wid >> 2;
    float acc[8][4];
    #pragma unroll
    for (int nt = 0; nt < 8; ++nt)
        #pragma unroll
        for (int q = 0; q < 4; ++q) acc[nt][q] = 0.f;

    const uint32_t ab = base + SM_A;
    const uint32_t wb = base + SM_W;

    issue_half(ab, srchi, srclo, m0, k0 + 0,   0u,   tid);
    issue_half(ab, srchi, srclo, m0, k0 + 128, 256u, tid);

    CP_WAIT(1); __syncthreads();
    compute_half(ab, wb, 0, acc, lane, mw, nw);
    CP_WAIT(0); __syncthreads();
    compute_half(ab, wb, 8, acc, lane, mw, nw);

    const int r4 = lane >> 2, c2 = (lane & 3) * 2;
    #pragma unroll
    for (int nt = 0; nt < 8; ++nt) {
        const int r0 = m0 + mw * 16 + r4;
        const int cc = n0 + nw * 64 + nt * 8 + c2;
        __stcg((float2*)&g_P[kc][r0][cc],     make_float2(acc[nt][0], acc[nt][1]));
        __stcg((float2*)&g_P[kc][r0 + 8][cc], make_float2(acc[nt][2], acc[nt][3]));
    }
}

// ---------------------------------------------------------------------------
// Persistent scan kernel. bids >= NCTA convert Wv on the spare SMs and exit
// (they never touch the barrier). Scan logic identical to the 6.07ms version.
// ---------------------------------------------------------------------------
__global__ __launch_bounds__(256) void rnn_persistent(
    const float* __restrict__ hidden, const int* __restrict__ tok,
    const float* __restrict__ emb,    const float* __restrict__ Wdt,
    const float* __restrict__ bdt,    const float* __restrict__ gamma,
    const float* __restrict__ beta,   const float* __restrict__ Wv,
    float* __restrict__ zout)
{
    extern __shared__ char smp[];
    const int tid = threadIdx.x;
    const int bid = blockIdx.x;

    // ---- converter CTAs: fp32 Wv -> bf16 hi/lo splits, then exit ----
    if (bid >= NCTA) {
        const int nx = gridDim.x - NCTA;
        const size_t total4 = (size_t)DIM * VOCAB / 4;
        const size_t stride = (size_t)nx * 256;
        for (size_t j = (size_t)(bid - NCTA) * 256 + tid; j < total4; j += stride) {
            const size_t idx = j * 4;
            const float4 v = __ldcg((const float4*)&Wv[idx]);
            const uint32_t h0 = pack_bf16x2(v.x, v.y);
            const uint32_t h1 = pack_bf16x2(v.z, v.w);
            const float lx = v.x - __bfloat162float(__float2bfloat16(v.x));
            const float ly = v.y - __bfloat162float(__float2bfloat16(v.y));
            const float lz = v.z - __bfloat162float(__float2bfloat16(v.z));
            const float lw = v.w - __bfloat162float(__float2bfloat16(v.w));
            __stcg((uint2*)&g_Wvhi[idx], make_uint2(h0, h1));
            __stcg((uint2*)&g_Wvlo[idx], make_uint2(pack_bf16x2(lx, ly), pack_bf16x2(lz, lw)));
        }
        return;
    }

    const uint32_t base = smem_u32(smp);
    __shared__ float red[2][2][4];

    const int mb = bid & 3, nc = (bid >> 2) & 7, kc = bid >> 5;
    const int m0 = mb * 64, n0 = nc * NT, k0 = kc * KT;

    const int row_sel = tid >> 7;
    const int b  = bid * 2 + row_sel;
    const int lt = tid & 127;
    const int d0 = lt * 8;
    const int wr = (tid >> 5) & 3;

    float ur[8], gm[8], bt[8];
    {
        const int tk0 = tok[(size_t)b * TLEN];
        float hv[8];
        const float4 h0 = *(const float4*)&hidden[(size_t)b * DIM + d0];
        const float4 h1 = *(const float4*)&hidden[(size_t)b * DIM + d0 + 4];
        hv[0]=h0.x; hv[1]=h0.y; hv[2]=h0.z; hv[3]=h0.w;
        hv[4]=h1.x; hv[5]=h1.y; hv[6]=h1.z; hv[7]=h1.w;
        const float4 u0 = *(const float4*)&emb[(size_t)tk0 * DIM + d0];
        const float4 u1 = *(const float4*)&emb[(size_t)tk0 * DIM + d0 + 4];
        ur[0]=u0.x; ur[1]=u0.y; ur[2]=u0.z; ur[3]=u0.w;
        ur[4]=u1.x; ur[5]=u1.y; ur[6]=u1.z; ur[7]=u1.w;
        split_store8(&g_Hhi[b][d0], &g_Hlo[b][d0], hv);
        split_store8(&g_Uhi[b][d0], &g_Ulo[b][d0], ur);
        const float4 g0 = *(const float4*)&gamma[d0];
        const float4 g1 = *(const float4*)&gamma[d0 + 4];
        gm[0]=g0.x; gm[1]=g0.y; gm[2]=g0.z; gm[3]=g0.w;
        gm[4]=g1.x; gm[5]=g1.y; gm[6]=g1.z; gm[7]=g1.w;
        const float4 b0 = *(const float4*)&beta[d0];
        const float4 b1 = *(const float4*)&beta[d0 + 4];
        bt[0]=b0.x; bt[1]=b0.y; bt[2]=b0.z; bt[3]=b0.w;
        bt[4]=b1.x; bt[5]=b1.y; bt[6]=b1.z; bt[7]=b1.w;
    }

    load_w(smp, Wdt, 1, k0, n0, tid);
    grid_barrier();
    gemm_step_mma(smp, base, &g_Hhi[0][0], &g_Hlo[0][0], m0, k0, n0, kc, tid);
    grid_barrier();

    float cre[8];
    {
        #pragma unroll
        for (int j = 0; j < 8; ++j) cre[j] = 0.f;
        #pragma unroll
        for (int j = 0; j < NK; ++j) {
            const float4 p0 = __ldcg((const float4*)&g_P[j][b][d0]);
            const float4 p1 = __ldcg((const float4*)&g_P[j][b][d0 + 4]);
            cre[0] += p0.x; cre[1] += p0.y; cre[2] += p0.z; cre[3] += p0.w;
            cre[4] += p1.x; cre[5] += p1.y; cre[6] += p1.z; cre[7] += p1.w;
        }
        const float4 bd0 = *(const float4*)&bdt[d0];
        const float4 bd1 = *(const float4*)&bdt[d0 + 4];
        cre[0]+=bd0.x; cre[1]+=bd0.y; cre[2]+=bd0.z; cre[3]+=bd0.w;
        cre[4]+=bd1.x; cre[5]+=bd1.y; cre[6]+=bd1.z; cre[7]+=bd1.w;
    }

    __syncthreads();
    load_w(smp, Wdt, 0, k0, n0, tid);
    grid_barrier();

    for (int t = 0; t < TLEN; ++t) {
        float ev[8];
        if (t < TLEN - 1) {
            const int tkn = tok[(size_t)b * TLEN + t + 1];
            const float4 e0 = *(const float4*)&emb[(size_t)tkn * DIM + d0];
            const float4 e1 = *(const float4*)&emb[(size_t)tkn * DIM + d0 + 4];
            ev[0]=e0.x; ev[1]=e0.y; ev[2]=e0.z; ev[3]=e0.w;
            ev[4]=e1.x; ev[5]=e1.y; ev[6]=e1.z; ev[7]=e1.w;
        }

        gemm_step_mma(smp, base, &g_Uhi[0][0], &g_Ulo[0][0], m0, k0, n0, kc, tid);
        grid_barrier();

        float y[8];
        #pragma unroll
        for (int j = 0; j < 8; ++j) y[j] = cre[j] + ur[j];
        #pragma unroll
        for (int j = 0; j < NK; ++j) {
            const float4 p0 = __ldcg((const float4*)&g_P[j][b][d0]);
            const float4 p1 = __ldcg((const float4*)&g_P[j][b][d0 + 4]);
            y[0] += p0.x; y[1] += p0.y; y[2] += p0.z; y[3] += p0.w;
            y[4] += p1.x; y[5] += p1.y; y[6] += p1.z; y[7] += p1.w;
        }

        float s1 = 0.f, s2 = 0.f;
        #pragma unroll
        for (int j = 0; j < 8; ++j) { s1 += y[j]; s2 += y[j] * y[j]; }
        #pragma unroll
        for (int o = 16; o; o >>= 1) {
            s1 += __shfl_xor_sync(0xffffffffu, s1, o);
            s2 += __shfl_xor_sync(0xffffffffu, s2, o);
        }
        if ((tid & 31) == 0) { red[row_sel][0][wr] = s1; red[row_sel][1][wr] = s2; }
        __syncthreads();
        float t1 = 0.f, t2 = 0.f;
        #pragma unroll
        for (int j = 0; j < 4; ++j) {
            t1 += red[row_sel][0][j];
            t2 += red[row_sel][1][j];
        }
        __syncthreads();

        const float mean = t1 * (1.f / DIM);
        const float var  = t2 * (1.f / DIM) - mean * mean;
        const float rstd = rsqrtf(var + 1e-5f);

        float sv[8];
        #pragma unroll
        for (int j = 0; j < 8; ++j)
            sv[j] = (y[j] - mean) * rstd * gm[j] + bt[j];

        if (t < TLEN - 1) {
            float un[8];
            #pragma unroll
            for (int j = 0; j < 8; ++j) { un[j] = sv[j] + ev[j]; ur[j] = un[j]; }
            split_store8(&g_Uhi[b][d0], &g_Ulo[b][d0], un);
        } else {
            *(float4*)&zout[(size_t)b * DIM + d0] =
                make_float4(sv[0], sv[1], sv[2], sv[3]);
            *(float4*)&zout[(size_t)b * DIM + d0 + 4] =
                make_float4(sv[4], sv[5], sv[6], sv[7]);
            split_store8(&g_Uhi[b][d0], &g_Ulo[b][d0], sv);  // z splits for logits
        }
        grid_barrier();
    }
}

// ---------------------------------------------------------------------------
// Tensor-core logits, double-buffered chunks.
// grid (4 m-blocks, 250 v-tiles); per CTA M=64 x N=128 x K=1024 (8 chunks).
// ---------------------------------------------------------------------------
__device__ __forceinline__ void lg_issue_chunk(uint32_t bufbase, int m0, int v0,
                                               int kg, int tid)
{
    #pragma unroll
    for (int t = 0; t < 8; ++t) {      // A: 2048 x 16B
        const int i  = tid + t * 256;
        const int sp = i >> 10;
        const int r  = (i >> 4) & 63;
        const int cc = i & 15;
        const __nv_bfloat16* src =
            (sp ? &g_Ulo[0][0] : &g_Uhi[0][0]) + (size_t)(m0 + r) * DIM + kg + cc * 8;
        cp_async16(bufbase + LG_A + (uint32_t)sp * LG_ASPL + (uint32_t)r * LG_STR
                   + (uint32_t)cc * 16u, src);
    }
    #pragma unroll
    for (int t = 0; t < 16; ++t) {     // B: 4096 x 16B
        const int i  = tid + t * 256;
        const int sp = i >> 11;
        const int r  = (i >> 4) & 127;
        const int cc = i & 15;
        const __nv_bfloat16* src =
            (sp ? g_Wvlo : g_Wvhi) + (size_t)(kg + r) * VOCAB + v0 + cc * 8;
        cp_async16(bufbase + LG_B + (uint32_t)sp * LG_BSPL + (uint32_t)r * LG_STR
                   + (uint32_t)cc * 16u, src);
    }
    CP_COMMIT();
}

__global__ __launch_bounds__(256) void logits_mma_kernel(
    const float* __restrict__ bv, float* __restrict__ L)
{
    extern __shared__ char smp[];
    const uint32_t base = smem_u32(smp);
    const int tid = threadIdx.x;
    const int m0 = blockIdx.x * 64;
    const int v0 = blockIdx.y * 128;
    const int lane = tid & 31, wid = tid >> 5;
    const int mw = wid & 3, nw = wid >> 2;

    float acc[8][4];
    #pragma unroll
    for (int nt = 0; nt < 8; ++nt)
        #pragma unroll
        for (int q = 0; q < 4; ++q) acc[nt][q] = 0.f;

    lg_issue_chunk(base + 0u,      m0, v0, 0,   tid);
    lg_issue_chunk(base + LG_BUF,  m0, v0, 128, tid);

    for (int c = 0; c < 8; ++c) {
        const uint32_t buf = base + (uint32_t)(c & 1) * LG_BUF;
        if (c < 6) { CP_WAIT(1); } else if (c == 6) { CP_WAIT(1); } else { CP_WAIT(0); }
        __syncthreads();

        const uint32_t ab = buf + LG_A;
        const uint32_t bb = buf + LG_B;
        #pragma unroll
        for (int ks = 0; ks < 8; ++ks) {
            const uint32_t arow = (uint32_t)(mw * 16 + (lane & 15));
            const uint32_t acol = (uint32_t)(ks * 32 + (lane >> 4) * 16);
            uint32_t ah[4], al[4];
            {
                const uint32_t off = arow * LG_STR + acol;
                ldm_x4(ah, ab + off);
                ldm_x4(al, ab + LG_ASPL + off);
            }
            const uint32_t krow_b = (uint32_t)(ks * 16 + (lane & 15));
            #pragma unroll
            for (int g = 0; g < 2; ++g) {
                uint32_t bh[4][2], bl[4][2];
                #pragma unroll
                for (int j = 0; j < 4; ++j) {
                    const uint32_t nb = (uint32_t)(nw * 128 + (g * 4 + j) * 16);
                    ldm_x2_t(bh[j], bb + 0u      + krow_b * LG_STR + nb);
                    ldm_x2_t(bl[j], bb + LG_BSPL + krow_b * LG_STR + nb);
                }
                #pragma unroll
                for (int j = 0; j < 4; ++j) {
                    float* a = acc[g * 4 + j];
                    mma_bf16(a, ah, bh[j]);
                    mma_bf16(a, ah, bl[j]);
                    mma_bf16(a, al, bh[j]);
                }
            }
        }
        __syncthreads();   // all warps done reading buf before re-issue

        if (c + 2 < 8)
            lg_issue_chunk(buf, m0, v0, (c + 2) * 128, tid);
    }

    const int r4 = lane >> 2, c2 = (lane & 3) * 2;
    #pragma unroll
    for (int nt = 0; nt < 8; ++nt) {
        const int r0 = m0 + mw * 16 + r4;
        const int cc = v0 + nw * 64 + nt * 8 + c2;
        const float2 bvv = *(const float2*)&bv[cc];
        *(float2*)&L[(size_t)r0 * VOCAB + cc] =
            make_float2(acc[nt][0] + bvv.x, acc[nt][1] + bvv.y);
        *(float2*)&L[(size_t)(r0 + 8) * VOCAB + cc] =
            make_float2(acc[nt][2] + bvv.x, acc[nt][3] + bvv.y);
    }
}

// ---------------------------------------------------------------------------
// In-place log_softmax over each row of L [BATCH][VOCAB]
// ---------------------------------------------------------------------------
__global__ __launch_bounds__(256) void logsoftmax_kernel(float* __restrict__ L)
{
    const int b   = blockIdx.x;
    const int tid = threadIdx.x;
    float* row = L + (size_t)b * VOCAB;
    __shared__ float red[8];

    float m = -1e30f;
    for (int i = tid * 4; i < VOCAB; i += 1024) {
        const float4 v = *(const float4*)&row[i];
        m = fmaxf(m, fmaxf(fmaxf(v.x, v.y), fmaxf(v.z, v.w)));
    }
    #pragma unroll
    for (int o = 16; o; o >>= 1) m = fmaxf(m, __shfl_xor_sync(0xffffffffu, m, o));
    if ((tid & 31) == 0) red[tid >> 5] = m;
    __syncthreads();
    float M = red[0];
    #pragma unroll
    for (int j = 1; j < 8; ++j) M = fmaxf(M, red[j]);
    __syncthreads();

    float s = 0.f;
    for (int i = tid * 4; i < VOCAB; i += 1024) {
        const float4 v = *(const float4*)&row[i];
        s += expf(v.x - M) + expf(v.y - M) + expf(v.z - M) + expf(v.w - M);
    }
    #pragma unroll
    for (int o = 16; o; o >>= 1) s += __shfl_xor_sync(0xffffffffu, s, o);
    if ((tid & 31) == 0) red[tid >> 5] = s;
    __syncthreads();
    float S = 0.f;
    #pragma unroll
    for (int j = 0; j < 8; ++j) S += red[j];
    const float lse = M + logf(S);

    for (int i = tid * 4; i < VOCAB; i += 1024) {
        float4 v = *(const float4*)&row[i];
        v.x -= lse; v.y -= lse; v.z -= lse; v.w -= lse;
        *(float4*)&row[i] = v;
    }
}

// ---------------------------------------------------------------------------
// kernel_launch — 3 graph nodes
// ---------------------------------------------------------------------------
extern "C" void kernel_launch(void* const* d_in, const int* in_sizes, int n_in,
                              void* d_out, int out_size)
{
    const float* hidden = (const float*)d_in[0];
    const int*   tok    = (const int*)  d_in[1];
    const float* emb    = (const float*)d_in[2];
    const float* Wdt    = (const float*)d_in[3];
    const float* bdt    = (const float*)d_in[4];
    const float* gamma  = (const float*)d_in[5];
    const float* beta   = (const float*)d_in[6];
    const float* Wv     = (const float*)d_in[7];
    const float* bv     = (const float*)d_in[8];

    float* zout = (float*)d_out;
    float* yout = zout + (size_t)BATCH * DIM;

    cudaFuncSetAttribute(rnn_persistent,
                         cudaFuncAttributeMaxDynamicSharedMemorySize, SMEM_BYTES);
    cudaFuncSetAttribute(logits_mma_kernel,
                         cudaFuncAttributeMaxDynamicSharedMemorySize, LG_SMEM);

    rnn_persistent<<<GRID_TOTAL, 256, SMEM_BYTES>>>(hidden, tok, emb, Wdt, bdt,
                                                    gamma, beta, Wv, zout);
    logits_mma_kernel<<<dim3(4, VOCAB / 128), 256, LG_SMEM>>>(bv, yout);
    logsoftmax_kernel<<<BATCH, 256>>>(yout);
}